// round 7
// baseline (speedup 1.0000x reference)
#include <cuda_runtime.h>
#include <cuda_fp16.h>
#include <math.h>

#define Nn 50000
#define Ee 600000
#define Dd 128
#define NB 391            // ceil(50000/128) row blocks
#define GRID 148
typedef unsigned long long ull;

// Scratch (allocation-free rule: __device__ globals)
__device__ __half g_mh[Nn * Dd];   // per-node messages (fp16 storage)
__device__ float g_sum[Nn * Dd];   // scatter accumulation (fp32)
__device__ float g_cnt[Nn];        // in-degree

// Packed fp32x2 FMA (Blackwell; ptxas never auto-fuses this)
#define FMA2(d, a, b) \
    asm("fma.rn.f32x2 %0, %1, %2, %3;" : "=l"(d) : "l"(a), "l"(b), "l"(d))

__device__ __forceinline__ ull splat2(float x) {
    ull d;
    asm("mov.b64 %0, {%1, %1};" : "=l"(d) : "f"(x));
    return d;
}
__device__ __forceinline__ void unpack2(ull v, float& lo, float& hi) {
    asm("mov.b64 {%0, %1}, %2;" : "=f"(lo), "=f"(hi) : "l"(v));
}
__device__ __forceinline__ unsigned h2_bits(__half2 h) {
    return *reinterpret_cast<unsigned*>(&h);
}
__device__ __forceinline__ __half2 bits_h2(unsigned u) {
    return *reinterpret_cast<__half2*>(&u);
}

// sA layout: k-major, stride 132 floats, row index XOR-swizzled by k.
// Keeps LDS.128 16B alignment; <=4-way bank conflicts on all access phases.
#define SIDX(k, r) (((k) * 132) + ((r) ^ ((((k) >> 2) & 7) << 2)))

// ---------------------------------------------------------------------------
// GEMM core: out[128r x 128c] = A[128r x 128k] * W[k][c].
// 512 thr: tx=tid&15 -> cols 8tx..8tx+7 (4 u64 col-pairs, natural W loads),
// ty=tid>>4 -> rows 4ty..4ty+3 (A splatted from register).
// acc[r][cp] = f32x2 over cols (2cp, 2cp+1) for row r.
// ---------------------------------------------------------------------------
__device__ __forceinline__ void gemm_cp(const float* __restrict__ sA,
                                        const float* __restrict__ sW,
                                        int tx, int ty4, ull acc[4][4]) {
    const float* wb = sW + (tx << 3);
#pragma unroll 4
    for (int k = 0; k < 128; k++) {
        float4 a = *reinterpret_cast<const float4*>(sA + SIDX(k, ty4));
        ulonglong2 w01 = *reinterpret_cast<const ulonglong2*>(wb + k * 128);
        ulonglong2 w23 = *reinterpret_cast<const ulonglong2*>(wb + k * 128 + 4);
        ull s0 = splat2(a.x), s1 = splat2(a.y), s2 = splat2(a.z), s3 = splat2(a.w);
        FMA2(acc[0][0], s0, w01.x); FMA2(acc[0][1], s0, w01.y);
        FMA2(acc[0][2], s0, w23.x); FMA2(acc[0][3], s0, w23.y);
        FMA2(acc[1][0], s1, w01.x); FMA2(acc[1][1], s1, w01.y);
        FMA2(acc[1][2], s1, w23.x); FMA2(acc[1][3], s1, w23.y);
        FMA2(acc[2][0], s2, w01.x); FMA2(acc[2][1], s2, w01.y);
        FMA2(acc[2][2], s2, w23.x); FMA2(acc[2][3], s2, w23.y);
        FMA2(acc[3][0], s3, w01.x); FMA2(acc[3][1], s3, w01.y);
        FMA2(acc[3][2], s3, w23.x); FMA2(acc[3][3], s3, w23.y);
    }
}

// ---------------------------------------------------------------------------
// Persistent fused 2-layer MLP. Each CTA loops over 128-row blocks.
// MODE 0: in = logmap0(x), out = g_mh (fp16); also zeroes g_sum/g_cnt slice.
// MODE 1: in = g_sum/(g_cnt+eps), out = expmap0(mlp(...)) -> Out (fp32)
// smem: sW1 64K + sW2 64K + sA 66K = 194.1 KB -> 1 CTA/SM.
// ---------------------------------------------------------------------------
template <int MODE>
__global__ __launch_bounds__(512, 1) void mlp_kernel(
    const float* __restrict__ X,
    const float* __restrict__ W1, const float* __restrict__ B1,
    const float* __restrict__ W2, const float* __restrict__ B2,
    float* __restrict__ Out) {
    extern __shared__ float smem[];
    float* sW1 = smem;               // [k*128 + c]
    float* sW2 = smem + 16384;
    float* sA  = smem + 32768;       // 128*132 = 16896 words
    __shared__ float sB1[128], sB2[128];

    const int tid = threadIdx.x;
    const int warp = tid >> 5, lane = tid & 31;
    const int tx = tid & 15, ty4 = (tid >> 4) << 2;

    // ---- stage both weight matrices + biases ONCE ----
    {
        const float4* s1 = reinterpret_cast<const float4*>(W1);
        const float4* s2 = reinterpret_cast<const float4*>(W2);
        float4* d1 = reinterpret_cast<float4*>(sW1);
        float4* d2 = reinterpret_cast<float4*>(sW2);
#pragma unroll
        for (int i = 0; i < 8; i++) {
            d1[tid + i * 512] = s1[tid + i * 512];
            d2[tid + i * 512] = s2[tid + i * 512];
        }
    }
    if (tid < 128) sB1[tid] = B1[tid];
    else if (tid < 256) sB2[tid - 128] = B2[tid - 128];

    for (int blk = blockIdx.x; blk < NB; blk += GRID) {
        const int row0 = blk * 128;

        // MODE 0: zero this block's accumulator slice
        if (MODE == 0) {
            float4 z = make_float4(0.f, 0.f, 0.f, 0.f);
#pragma unroll
            for (int i = 0; i < 8; i++) {
                int e = row0 * 128 + (tid + i * 512) * 4;
                if (e < Nn * Dd) *reinterpret_cast<float4*>(g_sum + e) = z;
            }
            if (tid < 128 && row0 + tid < Nn) g_cnt[row0 + tid] = 0.f;
        }

        // ---- stage input block (k-major, swizzled) with input transform ----
        for (int rr = warp; rr < 128; rr += 16) {
            const int r = row0 + rr;
            float4 v = make_float4(0.f, 0.f, 0.f, 0.f);
            if (r < Nn) {
                if (MODE == 0) {
                    v = reinterpret_cast<const float4*>(X + (size_t)r * 128)[lane];
                } else {
                    v = reinterpret_cast<const float4*>(g_sum + (size_t)r * 128)[lane];
                    float inv = 1.f / (g_cnt[r] + 1e-8f);
                    v.x *= inv; v.y *= inv; v.z *= inv; v.w *= inv;
                }
            }
            if (MODE == 0) {
                float ss = v.x * v.x + v.y * v.y + v.z * v.z + v.w * v.w;
#pragma unroll
                for (int o = 16; o > 0; o >>= 1)
                    ss += __shfl_xor_sync(0xffffffffu, ss, o);
                float nrm = sqrtf(ss);
                float nc = fminf(fmaxf(nrm, 1e-8f), 1.f - 1e-5f);
                float f = atanhf(nc) / nc;
                v.x *= f; v.y *= f; v.z *= f; v.w *= f;
            }
            const int k0 = lane * 4;
            sA[SIDX(k0 + 0, rr)] = v.x;
            sA[SIDX(k0 + 1, rr)] = v.y;
            sA[SIDX(k0 + 2, rr)] = v.z;
            sA[SIDX(k0 + 3, rr)] = v.w;
        }
        __syncthreads();

        // ---- phase 1: hidden = relu(A @ W1 + b1) ----
        ull acc[4][4];
#pragma unroll
        for (int r = 0; r < 4; r++)
#pragma unroll
            for (int cp = 0; cp < 4; cp++) acc[r][cp] = 0ull;

        gemm_cp(sA, sW1, tx, ty4, acc);
        __syncthreads();   // all reads of sA complete

        // write H back into sA (k-major over hidden cols)
        {
            float o[4][8];
#pragma unroll
            for (int r = 0; r < 4; r++)
#pragma unroll
                for (int cp = 0; cp < 4; cp++)
                    unpack2(acc[r][cp], o[r][2 * cp], o[r][2 * cp + 1]);
#pragma unroll
            for (int c = 0; c < 8; c++) {
                const int hc = tx * 8 + c;
                const float b = sB1[hc];
                float4 hv;
                hv.x = fmaxf(o[0][c] + b, 0.f);
                hv.y = fmaxf(o[1][c] + b, 0.f);
                hv.z = fmaxf(o[2][c] + b, 0.f);
                hv.w = fmaxf(o[3][c] + b, 0.f);
                *reinterpret_cast<float4*>(sA + SIDX(hc, ty4)) = hv;
            }
        }
        __syncthreads();

        // ---- phase 2: out = H @ W2 + b2 ----
#pragma unroll
        for (int r = 0; r < 4; r++)
#pragma unroll
            for (int cp = 0; cp < 4; cp++) acc[r][cp] = 0ull;

        gemm_cp(sA, sW2, tx, ty4, acc);

        // ---- epilogue ----
        {
            float o[4][8];
#pragma unroll
            for (int r = 0; r < 4; r++)
#pragma unroll
                for (int cp = 0; cp < 4; cp++) {
                    unpack2(acc[r][cp], o[r][2 * cp], o[r][2 * cp + 1]);
                    o[r][2 * cp]     += sB2[tx * 8 + 2 * cp];
                    o[r][2 * cp + 1] += sB2[tx * 8 + 2 * cp + 1];
                }

            if (MODE == 0) {
                // store messages as fp16 (one STG.128 per row)
#pragma unroll
                for (int r = 0; r < 4; r++) {
                    const int gr = row0 + ty4 + r;
                    if (gr < Nn) {
                        uint4 pk;
                        pk.x = h2_bits(__floats2half2_rn(o[r][0], o[r][1]));
                        pk.y = h2_bits(__floats2half2_rn(o[r][2], o[r][3]));
                        pk.z = h2_bits(__floats2half2_rn(o[r][4], o[r][5]));
                        pk.w = h2_bits(__floats2half2_rn(o[r][6], o[r][7]));
                        *reinterpret_cast<uint4*>(
                            reinterpret_cast<char*>(g_mh) +
                            ((size_t)gr * 128 + tx * 8) * 2) = pk;
                    }
                }
            } else {
                // expmap0: per-row norm, reduce across the 16 tx lanes
#pragma unroll
                for (int r = 0; r < 4; r++) {
                    float ss = 0.f;
#pragma unroll
                    for (int c = 0; c < 8; c++) ss += o[r][c] * o[r][c];
                    ss += __shfl_xor_sync(0xffffffffu, ss, 1);
                    ss += __shfl_xor_sync(0xffffffffu, ss, 2);
                    ss += __shfl_xor_sync(0xffffffffu, ss, 4);
                    ss += __shfl_xor_sync(0xffffffffu, ss, 8);
                    float nc = fmaxf(sqrtf(ss), 1e-8f);
                    float f = tanhf(nc) / nc;
                    const int gr = row0 + ty4 + r;
                    if (gr < Nn) {
                        float* p = Out + (size_t)gr * 128 + tx * 8;
                        *reinterpret_cast<float4*>(p) =
                            make_float4(o[r][0] * f, o[r][1] * f, o[r][2] * f, o[r][3] * f);
                        *reinterpret_cast<float4*>(p + 4) =
                            make_float4(o[r][4] * f, o[r][5] * f, o[r][6] * f, o[r][7] * f);
                    }
                }
            }
        }
        __syncthreads();   // protect sA before next block's staging
    }
}

// ---------------------------------------------------------------------------
// Scatter: one warp per edge. g_sum[dst] += fp32(g_mh[src]); g_cnt[dst] += 1.
// Lane reads 4 halves (LDG.64), converts, one RED.v4.f32.
// ---------------------------------------------------------------------------
__global__ __launch_bounds__(256) void scatter_kernel(const int* __restrict__ ei) {
    const int gw = (blockIdx.x * blockDim.x + threadIdx.x) >> 5;
    const int lane = threadIdx.x & 31;
    if (gw >= Ee) return;
    const int dst = ei[gw];         // edge_index[0] = row
    const int src = ei[Ee + gw];    // edge_index[1] = col
    uint2 raw = *reinterpret_cast<const uint2*>(
        reinterpret_cast<const char*>(g_mh) + ((size_t)src * 128 + lane * 4) * 2);
    float2 f0 = __half22float2(bits_h2(raw.x));
    float2 f1 = __half22float2(bits_h2(raw.y));
    float* p = g_sum + (size_t)dst * 128 + lane * 4;
    asm volatile("red.global.add.v4.f32 [%0], {%1,%2,%3,%4};"
                 :: "l"(p), "f"(f0.x), "f"(f0.y), "f"(f1.x), "f"(f1.y)
                 : "memory");
    if (lane == 0) atomicAdd(&g_cnt[dst], 1.0f);
}

// ---------------------------------------------------------------------------
extern "C" void kernel_launch(void* const* d_in, const int* in_sizes, int n_in,
                              void* d_out, int out_size) {
    const float* x  = (const float*)d_in[0];
    const int*   ei = (const int*)d_in[1];
    const float* w1 = (const float*)d_in[2];
    const float* b1 = (const float*)d_in[3];
    const float* w2 = (const float*)d_in[4];
    const float* b2 = (const float*)d_in[5];
    const float* w3 = (const float*)d_in[6];
    const float* b3 = (const float*)d_in[7];
    const float* w4 = (const float*)d_in[8];
    const float* b4 = (const float*)d_in[9];
    float* out = (float*)d_out;

    const size_t shmem = (size_t)(2 * 16384 + 128 * 132) * sizeof(float); // 198656 B
    static bool configured = false;
    if (!configured) {
        cudaFuncSetAttribute(mlp_kernel<0>, cudaFuncAttributeMaxDynamicSharedMemorySize, (int)shmem);
        cudaFuncSetAttribute(mlp_kernel<1>, cudaFuncAttributeMaxDynamicSharedMemorySize, (int)shmem);
        configured = true;
    }

    mlp_kernel<0><<<GRID, 512, shmem>>>(x, w1, b1, w2, b2, nullptr);
    scatter_kernel<<<(Ee + 7) / 8, 256>>>(ei);
    mlp_kernel<1><<<GRID, 512, shmem>>>(nullptr, w3, b3, w4, b4, out);
}

// round 12
// speedup vs baseline: 1.3810x; 1.3810x over previous
#include <cuda_runtime.h>
#include <cuda_fp16.h>
#include <math.h>

#define Nn 50000
#define Ee 600000
#define Dd 128
#define NB 391            // ceil(50000/128) row blocks
#define GRID 148
typedef unsigned long long ull;

// Scratch (allocation-free rule: __device__ globals)
__device__ __half g_mh[Nn * Dd];   // per-node messages (fp16 storage)
__device__ float g_sum[Nn * Dd];   // scatter accumulation (fp32)
__device__ float g_cnt[Nn];        // in-degree

// Packed fp32x2 FMA (Blackwell; ptxas never auto-fuses this)
#define FMA2(d, a, b) \
    asm("fma.rn.f32x2 %0, %1, %2, %3;" : "=l"(d) : "l"(a), "l"(b), "l"(d))

__device__ __forceinline__ ull splat2(float x) {
    ull d;
    asm("mov.b64 %0, {%1, %1};" : "=l"(d) : "f"(x));
    return d;
}
__device__ __forceinline__ void unpack2(ull v, float& lo, float& hi) {
    asm("mov.b64 {%0, %1}, %2;" : "=f"(lo), "=f"(hi) : "l"(v));
}
__device__ __forceinline__ unsigned h2_bits(__half2 h) {
    return *reinterpret_cast<unsigned*>(&h);
}
__device__ __forceinline__ __half2 bits_h2(unsigned u) {
    return *reinterpret_cast<__half2*>(&u);
}
__device__ __forceinline__ float fcomp(const float4& v, int i) {
    switch (i) { case 0: return v.x; case 1: return v.y; case 2: return v.z; default: return v.w; }
}

// ---------------------------------------------------------------------------
// GEMM core: out[128r x 128c] = A[128r x 128k] * W[k][c].
// sA row-major [r][128] (conflict-free everywhere: stores are contiguous
// per lane, GEMM reads are 16-lane broadcast).
// sW [k][128]. Thread (tx=tid&15, ty4=(tid>>4)*4) owns rows ty4..ty4+3 and
// cols {4tx..4tx+3, 64+4tx..64+4tx+3}: W loads are contiguous 16B per lane
// (no conflicts), each float4 = 2 natural u64 col-pair FFMA2 operands.
// acc[r][cp]: cp0=(4tx,4tx+1) cp1=(4tx+2,4tx+3) cp2=(64+4tx,..) cp3=(64+4tx+2,..)
// ---------------------------------------------------------------------------
__device__ __forceinline__ void gemm_rm(const float* __restrict__ sA,
                                        const float* __restrict__ sW,
                                        int tx, int ty4, ull acc[4][4]) {
    const float* ab = sA + ty4 * 128;
    const float* wb = sW + (tx << 2);
#pragma unroll 2
    for (int k = 0; k < 128; k += 4) {
        float4 a[4];
#pragma unroll
        for (int r = 0; r < 4; r++)
            a[r] = *reinterpret_cast<const float4*>(ab + r * 128 + k);
#pragma unroll
        for (int kk = 0; kk < 4; kk++) {
            ulonglong2 wlo = *reinterpret_cast<const ulonglong2*>(wb + (k + kk) * 128);
            ulonglong2 whi = *reinterpret_cast<const ulonglong2*>(wb + (k + kk) * 128 + 64);
#pragma unroll
            for (int r = 0; r < 4; r++) {
                ull s = splat2(fcomp(a[r], kk));
                FMA2(acc[r][0], s, wlo.x);
                FMA2(acc[r][1], s, wlo.y);
                FMA2(acc[r][2], s, whi.x);
                FMA2(acc[r][3], s, whi.y);
            }
        }
    }
}

// ---------------------------------------------------------------------------
// Persistent fused 2-layer MLP. Each CTA loops over 128-row blocks.
// MODE 0: in = logmap0(x), out = g_mh (fp16); also zeroes g_sum/g_cnt slice.
// MODE 1: in = g_sum/(g_cnt+eps), out = expmap0(mlp(...)) -> Out (fp32)
// smem: sW1 64K + sW2 64K + sA 64K = 192 KB -> 1 CTA/SM.
// ---------------------------------------------------------------------------
template <int MODE>
__global__ __launch_bounds__(512, 1) void mlp_kernel(
    const float* __restrict__ X,
    const float* __restrict__ W1, const float* __restrict__ B1,
    const float* __restrict__ W2, const float* __restrict__ B2,
    float* __restrict__ Out) {
    extern __shared__ float smem[];
    float* sW1 = smem;               // [k*128 + c]
    float* sW2 = smem + 16384;
    float* sA  = smem + 32768;       // [r*128 + k], row-major
    __shared__ float sB1[128], sB2[128];

    const int tid = threadIdx.x;
    const int warp = tid >> 5, lane = tid & 31;
    const int tx = tid & 15, ty4 = (tid >> 4) << 2;

    // ---- stage both weight matrices + biases ONCE ----
    {
        const float4* s1 = reinterpret_cast<const float4*>(W1);
        const float4* s2 = reinterpret_cast<const float4*>(W2);
        float4* d1 = reinterpret_cast<float4*>(sW1);
        float4* d2 = reinterpret_cast<float4*>(sW2);
#pragma unroll
        for (int i = 0; i < 8; i++) {
            d1[tid + i * 512] = s1[tid + i * 512];
            d2[tid + i * 512] = s2[tid + i * 512];
        }
    }
    if (tid < 128) sB1[tid] = B1[tid];
    else if (tid < 256) sB2[tid - 128] = B2[tid - 128];

    for (int blk = blockIdx.x; blk < NB; blk += GRID) {
        const int row0 = blk * 128;

        // MODE 0: zero this block's accumulator slice
        if (MODE == 0) {
            float4 z = make_float4(0.f, 0.f, 0.f, 0.f);
#pragma unroll
            for (int i = 0; i < 8; i++) {
                int e = row0 * 128 + (tid + i * 512) * 4;
                if (e < Nn * Dd) *reinterpret_cast<float4*>(g_sum + e) = z;
            }
            if (tid < 128 && row0 + tid < Nn) g_cnt[row0 + tid] = 0.f;
        }

        // ---- stage input block (row-major) with input transform ----
        for (int rr = warp; rr < 128; rr += 16) {
            const int r = row0 + rr;
            float4 v = make_float4(0.f, 0.f, 0.f, 0.f);
            if (r < Nn) {
                if (MODE == 0) {
                    v = reinterpret_cast<const float4*>(X + (size_t)r * 128)[lane];
                } else {
                    v = reinterpret_cast<const float4*>(g_sum + (size_t)r * 128)[lane];
                    float inv = 1.f / (g_cnt[r] + 1e-8f);
                    v.x *= inv; v.y *= inv; v.z *= inv; v.w *= inv;
                }
            }
            if (MODE == 0) {
                float ss = v.x * v.x + v.y * v.y + v.z * v.z + v.w * v.w;
#pragma unroll
                for (int o = 16; o > 0; o >>= 1)
                    ss += __shfl_xor_sync(0xffffffffu, ss, o);
                float nrm = sqrtf(ss);
                float nc = fminf(fmaxf(nrm, 1e-8f), 1.f - 1e-5f);
                float f = atanhf(nc) / nc;
                v.x *= f; v.y *= f; v.z *= f; v.w *= f;
            }
            *reinterpret_cast<float4*>(sA + rr * 128 + lane * 4) = v;  // conflict-free
        }
        __syncthreads();

        // ---- phase 1: hidden = relu(A @ W1 + b1) ----
        ull acc[4][4];
#pragma unroll
        for (int r = 0; r < 4; r++)
#pragma unroll
            for (int cp = 0; cp < 4; cp++) acc[r][cp] = 0ull;

        gemm_rm(sA, sW1, tx, ty4, acc);
        __syncthreads();   // all reads of sA complete

        // write H back into sA (row-major, contiguous 16B per lane)
#pragma unroll
        for (int r = 0; r < 4; r++) {
            float o[8];
#pragma unroll
            for (int cp = 0; cp < 4; cp++)
                unpack2(acc[r][cp], o[2 * cp], o[2 * cp + 1]);
            float4 h0, h1;
            h0.x = fmaxf(o[0] + sB1[4 * tx + 0], 0.f);
            h0.y = fmaxf(o[1] + sB1[4 * tx + 1], 0.f);
            h0.z = fmaxf(o[2] + sB1[4 * tx + 2], 0.f);
            h0.w = fmaxf(o[3] + sB1[4 * tx + 3], 0.f);
            h1.x = fmaxf(o[4] + sB1[64 + 4 * tx + 0], 0.f);
            h1.y = fmaxf(o[5] + sB1[64 + 4 * tx + 1], 0.f);
            h1.z = fmaxf(o[6] + sB1[64 + 4 * tx + 2], 0.f);
            h1.w = fmaxf(o[7] + sB1[64 + 4 * tx + 3], 0.f);
            *reinterpret_cast<float4*>(sA + (ty4 + r) * 128 + 4 * tx) = h0;
            *reinterpret_cast<float4*>(sA + (ty4 + r) * 128 + 64 + 4 * tx) = h1;
        }
        __syncthreads();

        // ---- phase 2: out = H @ W2 + b2 ----
#pragma unroll
        for (int r = 0; r < 4; r++)
#pragma unroll
            for (int cp = 0; cp < 4; cp++) acc[r][cp] = 0ull;

        gemm_rm(sA, sW2, tx, ty4, acc);

        // ---- epilogue ----
#pragma unroll
        for (int r = 0; r < 4; r++) {
            float o[8];
#pragma unroll
            for (int cp = 0; cp < 4; cp++)
                unpack2(acc[r][cp], o[2 * cp], o[2 * cp + 1]);
#pragma unroll
            for (int c = 0; c < 4; c++) {
                o[c]     += sB2[4 * tx + c];
                o[4 + c] += sB2[64 + 4 * tx + c];
            }
            const int gr = row0 + ty4 + r;

            if (MODE == 0) {
                if (gr < Nn) {
                    uint2 p0, p1;
                    p0.x = h2_bits(__floats2half2_rn(o[0], o[1]));
                    p0.y = h2_bits(__floats2half2_rn(o[2], o[3]));
                    p1.x = h2_bits(__floats2half2_rn(o[4], o[5]));
                    p1.y = h2_bits(__floats2half2_rn(o[6], o[7]));
                    char* base = reinterpret_cast<char*>(g_mh) + (size_t)gr * 256;
                    *reinterpret_cast<uint2*>(base + 4 * tx * 2) = p0;
                    *reinterpret_cast<uint2*>(base + (64 + 4 * tx) * 2) = p1;
                }
            } else {
                float ss = 0.f;
#pragma unroll
                for (int c = 0; c < 8; c++) ss += o[c] * o[c];
                ss += __shfl_xor_sync(0xffffffffu, ss, 1);
                ss += __shfl_xor_sync(0xffffffffu, ss, 2);
                ss += __shfl_xor_sync(0xffffffffu, ss, 4);
                ss += __shfl_xor_sync(0xffffffffu, ss, 8);
                float nc = fmaxf(sqrtf(ss), 1e-8f);
                float f = tanhf(nc) / nc;
                if (gr < Nn) {
                    float* p = Out + (size_t)gr * 128;
                    *reinterpret_cast<float4*>(p + 4 * tx) =
                        make_float4(o[0] * f, o[1] * f, o[2] * f, o[3] * f);
                    *reinterpret_cast<float4*>(p + 64 + 4 * tx) =
                        make_float4(o[4] * f, o[5] * f, o[6] * f, o[7] * f);
                }
            }
        }
        __syncthreads();   // protect sA before next block's staging
    }
}

// ---------------------------------------------------------------------------
// Scatter: one warp per edge. g_sum[dst] += fp32(g_mh[src]); g_cnt[dst] += 1.
// ---------------------------------------------------------------------------
__global__ __launch_bounds__(256) void scatter_kernel(const int* __restrict__ ei) {
    const int gw = (blockIdx.x * blockDim.x + threadIdx.x) >> 5;
    const int lane = threadIdx.x & 31;
    if (gw >= Ee) return;
    const int dst = ei[gw];         // edge_index[0] = row
    const int src = ei[Ee + gw];    // edge_index[1] = col
    uint2 raw = *reinterpret_cast<const uint2*>(
        reinterpret_cast<const char*>(g_mh) + ((size_t)src * 128 + lane * 4) * 2);
    float2 f0 = __half22float2(bits_h2(raw.x));
    float2 f1 = __half22float2(bits_h2(raw.y));
    float* p = g_sum + (size_t)dst * 128 + lane * 4;
    asm volatile("red.global.add.v4.f32 [%0], {%1,%2,%3,%4};"
                 :: "l"(p), "f"(f0.x), "f"(f0.y), "f"(f1.x), "f"(f1.y)
                 : "memory");
    if (lane == 0) atomicAdd(&g_cnt[dst], 1.0f);
}

// ---------------------------------------------------------------------------
extern "C" void kernel_launch(void* const* d_in, const int* in_sizes, int n_in,
                              void* d_out, int out_size) {
    const float* x  = (const float*)d_in[0];
    const int*   ei = (const int*)d_in[1];
    const float* w1 = (const float*)d_in[2];
    const float* b1 = (const float*)d_in[3];
    const float* w2 = (const float*)d_in[4];
    const float* b2 = (const float*)d_in[5];
    const float* w3 = (const float*)d_in[6];
    const float* b3 = (const float*)d_in[7];
    const float* w4 = (const float*)d_in[8];
    const float* b4 = (const float*)d_in[9];
    float* out = (float*)d_out;

    const size_t shmem = (size_t)(3 * 16384) * sizeof(float);   // 192 KB
    static bool configured = false;
    if (!configured) {
        cudaFuncSetAttribute(mlp_kernel<0>, cudaFuncAttributeMaxDynamicSharedMemorySize, (int)shmem);
        cudaFuncSetAttribute(mlp_kernel<1>, cudaFuncAttributeMaxDynamicSharedMemorySize, (int)shmem);
        configured = true;
    }

    mlp_kernel<0><<<GRID, 512, shmem>>>(x, w1, b1, w2, b2, nullptr);
    scatter_kernel<<<(Ee + 7) / 8, 256>>>(ei);
    mlp_kernel<1><<<GRID, 512, shmem>>>(nullptr, w3, b3, w4, b4, out);
}

// round 16
// speedup vs baseline: 1.7369x; 1.2577x over previous
#include <cuda_runtime.h>
#include <cuda_fp16.h>
#include <stdint.h>
#include <math.h>
#include <mma.h>

using namespace nvcuda;

#define Nn 50000
#define Ee 600000
#define NB 391            // ceil(50000/128) row blocks
#define GRID 148

// smem layout (bytes): sA h[128*136] @0 (34816), sW1 @34816, sW2 @69632,
// sC f32[128*132] @104448 (67584) -> total 172032
#define SA_STRIDE 136
#define SC_STRIDE 132
#define SMEM_BYTES 172032

// Scratch (allocation-free rule: __device__ globals)
__device__ __half g_mh[Nn * 128];  // per-node messages (fp16)
__device__ float g_sum[Nn * 128];  // scatter accumulation (fp32)
__device__ float g_cnt[Nn];        // in-degree

__device__ __forceinline__ unsigned h2_bits(__half2 h) {
    return *reinterpret_cast<unsigned*>(&h);
}
__device__ __forceinline__ __half2 bits_h2(unsigned u) {
    return *reinterpret_cast<__half2*>(&u);
}

// ---------------------------------------------------------------------------
// WMMA GEMM: sC[128][132] = sA[128][136](f16, row-major over k)
//                         @ sW[c][k] (f16, W transposed -> col_major B).
// 16 warps: wr=w&3 (32-row band), wc=w>>2 (32-col band); 2x2 16x16 frags.
// ---------------------------------------------------------------------------
__device__ __forceinline__ void gemm_wmma(const __half* sA, const __half* sW,
                                          float* sC, int wr, int wc) {
    wmma::fragment<wmma::accumulator, 16, 16, 16, float> acc[2][2];
#pragma unroll
    for (int i = 0; i < 2; i++)
#pragma unroll
        for (int j = 0; j < 2; j++) wmma::fill_fragment(acc[i][j], 0.0f);

#pragma unroll
    for (int ks = 0; ks < 128; ks += 16) {
        wmma::fragment<wmma::matrix_a, 16, 16, 16, __half, wmma::row_major> af[2];
        wmma::fragment<wmma::matrix_b, 16, 16, 16, __half, wmma::col_major> bf[2];
        wmma::load_matrix_sync(af[0], sA + (32 * wr) * SA_STRIDE + ks, SA_STRIDE);
        wmma::load_matrix_sync(af[1], sA + (32 * wr + 16) * SA_STRIDE + ks, SA_STRIDE);
        wmma::load_matrix_sync(bf[0], sW + (32 * wc) * SA_STRIDE + ks, SA_STRIDE);
        wmma::load_matrix_sync(bf[1], sW + (32 * wc + 16) * SA_STRIDE + ks, SA_STRIDE);
#pragma unroll
        for (int i = 0; i < 2; i++)
#pragma unroll
            for (int j = 0; j < 2; j++)
                wmma::mma_sync(acc[i][j], af[i], bf[j], acc[i][j]);
    }
#pragma unroll
    for (int i = 0; i < 2; i++)
#pragma unroll
        for (int j = 0; j < 2; j++)
            wmma::store_matrix_sync(sC + (32 * wr + 16 * i) * SC_STRIDE + 32 * wc + 16 * j,
                                    acc[i][j], SC_STRIDE, wmma::mem_row_major);
}

// ---------------------------------------------------------------------------
// Persistent fused 2-layer MLP via WMMA. 512 threads. Block = 128 rows.
// MODE 0: in = logmap0(x) -> g_mh (fp16); zeroes g_sum/g_cnt slice.
// MODE 1: in = g_sum/(g_cnt+eps) -> expmap0(mlp) -> Out (fp32)
// ---------------------------------------------------------------------------
template <int MODE>
__global__ __launch_bounds__(512, 1) void mlp_wmma(
    const float* __restrict__ X,
    const float* __restrict__ W1, const float* __restrict__ B1,
    const float* __restrict__ W2, const float* __restrict__ B2,
    float* __restrict__ Out) {
    extern __shared__ __align__(16) unsigned char smem[];
    __half* sA  = reinterpret_cast<__half*>(smem);
    __half* sW1 = sA + 128 * SA_STRIDE;
    __half* sW2 = sW1 + 128 * SA_STRIDE;
    float*  sC  = reinterpret_cast<float*>(smem + 104448);
    __shared__ float sB1[128], sB2[128];

    const int tid = threadIdx.x;
    const int w = tid >> 5, lane = tid & 31;
    const int wr = w & 3, wc = w >> 2;

    // ---- stage weights transposed to fp16: sW[c][k] = W[k][c] ----
    for (int i = tid; i < 4096; i += 512) {
        const int c = i >> 5;
        const int k0 = (i & 31) * 4;
        uint2 p;
        p.x = h2_bits(__floats2half2_rn(W1[(k0 + 0) * 128 + c], W1[(k0 + 1) * 128 + c]));
        p.y = h2_bits(__floats2half2_rn(W1[(k0 + 2) * 128 + c], W1[(k0 + 3) * 128 + c]));
        *reinterpret_cast<uint2*>(sW1 + c * SA_STRIDE + k0) = p;
        p.x = h2_bits(__floats2half2_rn(W2[(k0 + 0) * 128 + c], W2[(k0 + 1) * 128 + c]));
        p.y = h2_bits(__floats2half2_rn(W2[(k0 + 2) * 128 + c], W2[(k0 + 3) * 128 + c]));
        *reinterpret_cast<uint2*>(sW2 + c * SA_STRIDE + k0) = p;
    }
    if (tid < 128) sB1[tid] = B1[tid];
    else if (tid < 256) sB2[tid - 128] = B2[tid - 128];
    __syncthreads();

    for (int blk = blockIdx.x; blk < NB; blk += GRID) {
        const int row0 = blk * 128;

        // MODE 0: zero this block's accumulator slice
        if (MODE == 0) {
            float4 z = make_float4(0.f, 0.f, 0.f, 0.f);
#pragma unroll
            for (int i = 0; i < 8; i++) {
                int e = row0 * 128 + (tid + i * 512) * 4;
                if (e < Nn * 128) *reinterpret_cast<float4*>(g_sum + e) = z;
            }
            if (tid < 128 && row0 + tid < Nn) g_cnt[row0 + tid] = 0.f;
        }

        // ---- stage input block (fp16 row-major) with input transform ----
        for (int rr = w; rr < 128; rr += 16) {
            const int r = row0 + rr;
            float4 v = make_float4(0.f, 0.f, 0.f, 0.f);
            if (r < Nn) {
                if (MODE == 0) {
                    v = reinterpret_cast<const float4*>(X + (size_t)r * 128)[lane];
                } else {
                    v = reinterpret_cast<const float4*>(g_sum + (size_t)r * 128)[lane];
                    float inv = 1.f / (g_cnt[r] + 1e-8f);
                    v.x *= inv; v.y *= inv; v.z *= inv; v.w *= inv;
                }
            }
            if (MODE == 0) {
                float ss = v.x * v.x + v.y * v.y + v.z * v.z + v.w * v.w;
#pragma unroll
                for (int o = 16; o > 0; o >>= 1)
                    ss += __shfl_xor_sync(0xffffffffu, ss, o);
                float nrm = sqrtf(ss);
                float nc = fminf(fmaxf(nrm, 1e-8f), 1.f - 1e-5f);
                float f = atanhf(nc) / nc;
                v.x *= f; v.y *= f; v.z *= f; v.w *= f;
            }
            uint2 p;
            p.x = h2_bits(__floats2half2_rn(v.x, v.y));
            p.y = h2_bits(__floats2half2_rn(v.z, v.w));
            *reinterpret_cast<uint2*>(sA + rr * SA_STRIDE + lane * 4) = p;
        }
        __syncthreads();

        // ---- GEMM 1: sC = A @ W1^T ----
        gemm_wmma(sA, sW1, sC, wr, wc);
        __syncthreads();

        // ---- epilogue 1: H = relu(sC + b1) -> fp16 sA ----
        {
            const int r = tid >> 2;
            const int c0 = (tid & 3) * 32;
            const float* src = sC + r * SC_STRIDE + c0;
            uint2 pk[4];
#pragma unroll
            for (int q = 0; q < 4; q++) {
                float4 a = *reinterpret_cast<const float4*>(src + 8 * q);
                float4 b = *reinterpret_cast<const float4*>(src + 8 * q + 4);
                float o0 = fmaxf(a.x + sB1[c0 + 8 * q + 0], 0.f);
                float o1 = fmaxf(a.y + sB1[c0 + 8 * q + 1], 0.f);
                float o2 = fmaxf(a.z + sB1[c0 + 8 * q + 2], 0.f);
                float o3 = fmaxf(a.w + sB1[c0 + 8 * q + 3], 0.f);
                float o4 = fmaxf(b.x + sB1[c0 + 8 * q + 4], 0.f);
                float o5 = fmaxf(b.y + sB1[c0 + 8 * q + 5], 0.f);
                float o6 = fmaxf(b.z + sB1[c0 + 8 * q + 6], 0.f);
                float o7 = fmaxf(b.w + sB1[c0 + 8 * q + 7], 0.f);
                pk[q].x = h2_bits(__floats2half2_rn(o0, o1));
                pk[q].y = h2_bits(__floats2half2_rn(o2, o3));
                uint2 hi;
                hi.x = h2_bits(__floats2half2_rn(o4, o5));
                hi.y = h2_bits(__floats2half2_rn(o6, o7));
                *reinterpret_cast<uint2*>(sA + r * SA_STRIDE + c0 + 8 * q) = pk[q];
                *reinterpret_cast<uint2*>(sA + r * SA_STRIDE + c0 + 8 * q + 4) = hi;
            }
        }
        __syncthreads();

        // ---- GEMM 2: sC = H @ W2^T ----
        gemm_wmma(sA, sW2, sC, wr, wc);
        __syncthreads();

        // ---- epilogue 2 ----
        {
            const int r = tid >> 2;
            const int c0 = (tid & 3) * 32;
            const int gr = row0 + r;
            float o[32];
            const float* src = sC + r * SC_STRIDE + c0;
#pragma unroll
            for (int q = 0; q < 8; q++) {
                float4 a = *reinterpret_cast<const float4*>(src + 4 * q);
                o[4 * q + 0] = a.x + sB2[c0 + 4 * q + 0];
                o[4 * q + 1] = a.y + sB2[c0 + 4 * q + 1];
                o[4 * q + 2] = a.z + sB2[c0 + 4 * q + 2];
                o[4 * q + 3] = a.w + sB2[c0 + 4 * q + 3];
            }

            if (MODE == 0) {
                if (gr < Nn) {
                    char* base = reinterpret_cast<char*>(g_mh) + ((size_t)gr * 128 + c0) * 2;
#pragma unroll
                    for (int q = 0; q < 2; q++) {
                        uint4 pk;
                        pk.x = h2_bits(__floats2half2_rn(o[16 * q + 0],  o[16 * q + 1]));
                        pk.y = h2_bits(__floats2half2_rn(o[16 * q + 2],  o[16 * q + 3]));
                        pk.z = h2_bits(__floats2half2_rn(o[16 * q + 4],  o[16 * q + 5]));
                        pk.w = h2_bits(__floats2half2_rn(o[16 * q + 6],  o[16 * q + 7]));
                        uint4 pk2;
                        pk2.x = h2_bits(__floats2half2_rn(o[16 * q + 8],  o[16 * q + 9]));
                        pk2.y = h2_bits(__floats2half2_rn(o[16 * q + 10], o[16 * q + 11]));
                        pk2.z = h2_bits(__floats2half2_rn(o[16 * q + 12], o[16 * q + 13]));
                        pk2.w = h2_bits(__floats2half2_rn(o[16 * q + 14], o[16 * q + 15]));
                        *reinterpret_cast<uint4*>(base + 32 * q) = pk;
                        *reinterpret_cast<uint4*>(base + 32 * q + 16) = pk2;
                    }
                }
            } else {
                float ss = 0.f;
#pragma unroll
                for (int c = 0; c < 32; c++) ss += o[c] * o[c];
                // 4 threads (same quad, same warp) hold this row's 4 col-quarters
                ss += __shfl_xor_sync(0xffffffffu, ss, 1);
                ss += __shfl_xor_sync(0xffffffffu, ss, 2);
                float nc = fmaxf(sqrtf(ss), 1e-8f);
                float f = tanhf(nc) / nc;
                if (gr < Nn) {
                    float4* p = reinterpret_cast<float4*>(Out + (size_t)gr * 128 + c0);
#pragma unroll
                    for (int q = 0; q < 8; q++)
                        p[q] = make_float4(o[4 * q] * f, o[4 * q + 1] * f,
                                           o[4 * q + 2] * f, o[4 * q + 3] * f);
                }
            }
        }
        __syncthreads();   // sC reads done before next block's GEMM1; sA reuse
    }
}

// ---------------------------------------------------------------------------
// Scatter: one warp per edge. g_sum[dst] += fp32(g_mh[src]); g_cnt[dst] += 1.
// ---------------------------------------------------------------------------
__global__ __launch_bounds__(256) void scatter_kernel(const int* __restrict__ ei) {
    const int gw = (blockIdx.x * blockDim.x + threadIdx.x) >> 5;
    const int lane = threadIdx.x & 31;
    if (gw >= Ee) return;
    const int dst = ei[gw];         // edge_index[0] = row
    const int src = ei[Ee + gw];    // edge_index[1] = col
    uint2 raw = *reinterpret_cast<const uint2*>(
        reinterpret_cast<const char*>(g_mh) + ((size_t)src * 128 + lane * 4) * 2);
    float2 f0 = __half22float2(bits_h2(raw.x));
    float2 f1 = __half22float2(bits_h2(raw.y));
    float* p = g_sum + (size_t)dst * 128 + lane * 4;
    asm volatile("red.global.add.v4.f32 [%0], {%1,%2,%3,%4};"
                 :: "l"(p), "f"(f0.x), "f"(f0.y), "f"(f1.x), "f"(f1.y)
                 : "memory");
    if (lane == 0) atomicAdd(&g_cnt[dst], 1.0f);
}

// ---------------------------------------------------------------------------
extern "C" void kernel_launch(void* const* d_in, const int* in_sizes, int n_in,
                              void* d_out, int out_size) {
    const float* x  = (const float*)d_in[0];
    const int*   ei = (const int*)d_in[1];
    const float* w1 = (const float*)d_in[2];
    const float* b1 = (const float*)d_in[3];
    const float* w2 = (const float*)d_in[4];
    const float* b2 = (const float*)d_in[5];
    const float* w3 = (const float*)d_in[6];
    const float* b3 = (const float*)d_in[7];
    const float* w4 = (const float*)d_in[8];
    const float* b4 = (const float*)d_in[9];
    float* out = (float*)d_out;

    static bool configured = false;
    if (!configured) {
        cudaFuncSetAttribute(mlp_wmma<0>, cudaFuncAttributeMaxDynamicSharedMemorySize, SMEM_BYTES);
        cudaFuncSetAttribute(mlp_wmma<1>, cudaFuncAttributeMaxDynamicSharedMemorySize, SMEM_BYTES);
        configured = true;
    }

    mlp_wmma<0><<<GRID, 512, SMEM_BYTES>>>(x, w1, b1, w2, b2, nullptr);
    scatter_kernel<<<(Ee + 7) / 8, 256>>>(ei);
    mlp_wmma<1><<<GRID, 512, SMEM_BYTES>>>(nullptr, w3, b3, w4, b4, out);
}